// round 7
// baseline (speedup 1.0000x reference)
#include <cuda_runtime.h>
#include <cuda_bf16.h>
#include <cstdint>

typedef unsigned int u32;

#define E_TOT   200000
#define GRID    148
#define UNITS   12500           // 20 r-values x 625 b-blocks of 16
#define USTRIDE (GRID * 8)

#define OFF_W0H 0
#define OFF_W0L 4096
#define OFF_W1H 8192
#define OFF_W1L 40960
#define OFF_TH  73728
#define OFF_TL  139264
#define OFF_TB  204800
#define OFF_B0  205824
#define OFF_B1  206336
#define SMEM_BYTES 206848

__device__ uint4 gWimg[SMEM_BYTES / 16];

// XOR-swizzled byte offset within a 256B-row bf16 image: row n, col k (0..127)
__host__ __device__ __forceinline__ u32 sw_off(int n, int k) {
    int chunk = k >> 3;
    return (u32)(n * 256 + (((chunk ^ (n & 7)) << 4) | ((k & 7) << 1)));
}

__device__ __forceinline__ void put_hl(u32 offh, u32 offl, u32 boff, float v) {
    char* img = (char*)gWimg;
    __nv_bfloat16 h = __float2bfloat16(v);
    __nv_bfloat16 l = __float2bfloat16(v - __bfloat162float(h));
    *(__nv_bfloat16*)(img + offh + boff) = h;
    *(__nv_bfloat16*)(img + offl + boff) = l;
}

__global__ void prep(const float* __restrict__ W0, const float* __restrict__ W1,
                     const float* __restrict__ b0, const float* __restrict__ b1,
                     const float* __restrict__ W2, const float* __restrict__ b2)
{
    int blk = blockIdx.x, tid = threadIdx.x;
    if (blk < 72) {
        int id = blk * 256 + tid;
        if (id < 2048) {                   // W0 [128n][16k], 32B rows, no swizzle
            int n = id >> 4, k = id & 15;
            put_hl(OFF_W0H, OFF_W0L, (u32)(n * 32 + k * 2), W0[id]);
        } else if (id < 2048 + 16384) {    // W1 [128n][128k], swizzled
            int j = id - 2048;
            put_hl(OFF_W1H, OFF_W1L, sw_off(j >> 7, j & 127), W1[j]);
        }
        if (id < 128) {
            *(float*)((char*)gWimg + OFF_B0 + id * 4) = b0[id];
            *(float*)((char*)gWimg + OFF_B1 + id * 4) = b1[id];
        }
    } else {
        int row = 2 * (blk - 72) + (tid >> 7);   // 0..255 = m*32 + o
        int m = row >> 5, o = row & 31;
        int j = tid & 127;
        float s = 0.f;
        for (int i = 0; i < 4 * (m + 1); ++i) s += W2[(o * 32 + i) * 128 + j];
        put_hl(OFF_TH, OFF_TL, sw_off(row, j), s);
        if (j == 0) {
            float sb = 0.f;
            for (int i = 0; i < 4 * (m + 1); ++i) sb += b2[o * 32 + i];
            *(float*)((char*)gWimg + OFF_TB + row * 4) = sb;
        }
    }
}

// ---------------------------------------------------------------------------
__device__ __forceinline__ u32 smem_u32(const void* p) {
    u32 a;
    asm("{ .reg .u64 t; cvta.to.shared.u64 t, %1; cvt.u32.u64 %0, t; }" : "=r"(a) : "l"(p));
    return a;
}
__device__ __forceinline__ void ldsm4(u32* r, u32 a) {
    asm volatile("ldmatrix.sync.aligned.m8n8.x4.shared.b16 {%0,%1,%2,%3}, [%4];"
        : "=r"(r[0]), "=r"(r[1]), "=r"(r[2]), "=r"(r[3]) : "r"(a));
}
__device__ __forceinline__ void mma(float* d, const u32* a, const u32* b) {
    asm volatile("mma.sync.aligned.m16n8k16.row.col.f32.bf16.bf16.f32 "
        "{%0,%1,%2,%3}, {%4,%5,%6,%7}, {%8,%9}, {%0,%1,%2,%3};"
        : "+f"(d[0]), "+f"(d[1]), "+f"(d[2]), "+f"(d[3])
        : "r"(a[0]), "r"(a[1]), "r"(a[2]), "r"(a[3]), "r"(b[0]), "r"(b[1]));
}
// 6-mma split-product group with acc/acc4 interleaving (dep distance 2)
__device__ __forceinline__ void mma6(float* acc, const u32* ah, const u32* al,
                                     const u32* bh, const u32* bl)
{
    mma(acc,     ah, bh);
    mma(acc + 4, ah, bh + 2);
    mma(acc,     ah, bl);
    mma(acc + 4, ah, bl + 2);
    mma(acc,     al, bh);
    mma(acc + 4, al, bh + 2);
}
__device__ __forceinline__ u32 packhl(float f0, float f1, u32& lo) {
    u32 h;
    asm("cvt.rn.bf16x2.f32 %0, %1, %2;" : "=r"(h) : "f"(f1), "f"(f0));
    float h0 = __uint_as_float(h << 16);
    float h1 = __uint_as_float(h & 0xffff0000u);
    asm("cvt.rn.bf16x2.f32 %0, %1, %2;" : "=r"(lo) : "f"(f1 - h1), "f"(f0 - h0));
    return h;
}
__device__ __forceinline__ float relu(float x) { return fmaxf(x, 0.f); }

__global__ void __launch_bounds__(256, 1)
msg_kernel(const float* __restrict__ h_w, const float* __restrict__ e_vw,
           float* __restrict__ out)
{
    extern __shared__ unsigned char sraw[];
    const int t = threadIdx.x, w = t >> 5, lane = t & 31;
    const int lr = lane & 7, g = lane >> 3, q = lane & 3;
    const int kc = 2 * q;
    const int el = lane >> 2;

    // stage weight image (202KB)
    {
        uint4* dst = (uint4*)sraw;
        for (int i = t; i < SMEM_BYTES / 16; i += 256) dst[i] = gWimg[i];
    }
    __syncthreads();

    const u32 sb = smem_u32(sraw);
    const float* b0s = (const float*)(sraw + OFF_B0);
    const float* b1s = (const float*)(sraw + OFF_B1);
    const float* Tbs = (const float*)(sraw + OFF_TB);

    // GEMM1 per-ntp address bases (unit-invariant)
    u32 rb1[8], sx1[8];
    #pragma unroll
    for (int ntp = 0; ntp < 8; ++ntp) {
        int n = (2 * ntp + (g >> 1)) * 8 + lr;
        rb1[ntp] = sb + OFF_W1H + n * 256;
        sx1[ntp] = (u32)(n & 7) << 4;
    }
    const u32 kxor = (u32)(g & 1) << 4;    // (2s+(g&1))<<4 = (s<<5) ^ kxor

    const int u0i = blockIdx.x * 8 + w;

    // ---- prefetch unit u0 (e rows + h_w values) ----
    float2 Pe[4];
    float Ph[6];
    {
        int uu = u0i;
        int r = uu % 20, bblk = uu / 20;
        int nb0 = bblk * 16 + el, nb1 = nb0 + 8;
        size_t ge0 = (size_t)nb0 * 20 + r, ge1 = (size_t)nb1 * 20 + r;
        int rm = (r * 32) % 20;
        int i1 = rm ? 20 - rm : 20;
        int v0 = (r * 32) / 20;
        bool hasB = (i1 + 20) < 32;
        Pe[0] = *(const float2*)(e_vw + ge0 * 16 + kc);
        Pe[1] = *(const float2*)(e_vw + ge0 * 16 + kc + 8);
        Pe[2] = *(const float2*)(e_vw + ge1 * 16 + kc);
        Pe[3] = *(const float2*)(e_vw + ge1 * 16 + kc + 8);
        Ph[0] = h_w[nb0 * 32 + v0]; Ph[1] = h_w[nb0 * 32 + v0 + 1];
        Ph[2] = hasB ? h_w[nb0 * 32 + v0 + 2] : 0.f;
        Ph[3] = h_w[nb1 * 32 + v0]; Ph[4] = h_w[nb1 * 32 + v0 + 1];
        Ph[5] = hasB ? h_w[nb1 * 32 + v0 + 2] : 0.f;
    }

    for (int u = u0i; u < UNITS; u += USTRIDE) {
        const int r = u % 20, bblk = u / 20;
        const int nb0 = bblk * 16 + el;
        const size_t ge0 = (size_t)nb0 * 20 + r;
        const size_t ge1 = ge0 + 160;      // (nb0+8)*20 + r

        // ---- warp-uniform telescoping structure ----
        const int rm = (r * 32) % 20;
        const int i1 = rm ? 20 - rm : 20;
        const int mA = (i1 >> 2) - 1;
        const bool hasB = (i1 + 20) < 32;
        const int mB = hasB ? ((i1 + 20) >> 2) - 1 : 7;

        // ---- consume prefetched values ----
        float cA0 = Ph[0] - Ph[1], cA1 = Ph[3] - Ph[4];
        float cB0 = 0.f, cB1 = 0.f, c70 = Ph[1], c71 = Ph[4];
        if (hasB) { cB0 = Ph[1] - Ph[2]; cB1 = Ph[4] - Ph[5]; c70 = Ph[2]; c71 = Ph[5]; }

        u32 ah[4], al[4];
        ah[0] = packhl(Pe[0].x, Pe[0].y, al[0]);
        ah[1] = packhl(Pe[2].x, Pe[2].y, al[1]);
        ah[2] = packhl(Pe[1].x, Pe[1].y, al[2]);
        ah[3] = packhl(Pe[3].x, Pe[3].y, al[3]);

        // ---- prefetch next unit (latency hidden behind all three GEMMs) ----
        {
            int un = u + USTRIDE;
            if (un < UNITS) {
                int rn = un % 20, bbn = un / 20;
                int n0 = bbn * 16 + el, n1 = n0 + 8;
                size_t g0 = (size_t)n0 * 20 + rn, g1 = (size_t)n1 * 20 + rn;
                int rmn = (rn * 32) % 20;
                int i1n = rmn ? 20 - rmn : 20;
                int v0n = (rn * 32) / 20;
                bool hBn = (i1n + 20) < 32;
                Pe[0] = *(const float2*)(e_vw + g0 * 16 + kc);
                Pe[1] = *(const float2*)(e_vw + g0 * 16 + kc + 8);
                Pe[2] = *(const float2*)(e_vw + g1 * 16 + kc);
                Pe[3] = *(const float2*)(e_vw + g1 * 16 + kc + 8);
                Ph[0] = h_w[n0 * 32 + v0n]; Ph[1] = h_w[n0 * 32 + v0n + 1];
                Ph[2] = hBn ? h_w[n0 * 32 + v0n + 2] : 0.f;
                Ph[3] = h_w[n1 * 32 + v0n]; Ph[4] = h_w[n1 * 32 + v0n + 1];
                Ph[5] = hBn ? h_w[n1 * 32 + v0n + 2] : 0.f;
            }
        }

        // ---- GEMM0: x1acc = e @ W0^T (K=16); 8 independent ntp groups ----
        float acc[64];
        #pragma unroll
        for (int i = 0; i < 64; ++i) acc[i] = 0.f;
        #pragma unroll
        for (int ntp = 0; ntp < 8; ++ntp) {
            int n = (2 * ntp + (g >> 1)) * 8 + lr;
            u32 ad = sb + OFF_W0H + n * 32 + (g & 1) * 16;
            u32 bh[4], bl[4];
            ldsm4(bh, ad);
            ldsm4(bl, ad + (OFF_W0L - OFF_W0H));
            mma6(acc + 8 * ntp, ah, al, bh, bl);
        }

        // ---- bias + relu -> x1 A-fragments ----
        u32 x1h[8][4], x1l[8][4];
        #pragma unroll
        for (int s = 0; s < 8; ++s) {
            int n0 = 16 * s + kc;
            float bb00 = b0s[n0], bb01 = b0s[n0 + 1], bb10 = b0s[n0 + 8], bb11 = b0s[n0 + 9];
            const float* A = acc + 8 * s;
            x1h[s][0] = packhl(relu(A[0] + bb00), relu(A[1] + bb01), x1l[s][0]);
            x1h[s][1] = packhl(relu(A[2] + bb00), relu(A[3] + bb01), x1l[s][1]);
            x1h[s][2] = packhl(relu(A[4] + bb10), relu(A[5] + bb11), x1l[s][2]);
            x1h[s][3] = packhl(relu(A[6] + bb10), relu(A[7] + bb11), x1l[s][3]);
        }

        // ---- GEMM1: x2acc = x1 @ W1^T (K=128); k-outer / ntp-inner ----
        #pragma unroll
        for (int i = 0; i < 64; ++i) acc[i] = 0.f;
        #pragma unroll
        for (int s = 0; s < 8; ++s) {
            u32 kx = ((u32)s << 5) ^ kxor;
            #pragma unroll
            for (int ntp = 0; ntp < 8; ++ntp) {
                u32 ad = rb1[ntp] + (kx ^ sx1[ntp]);
                u32 bh[4], bl[4];
                ldsm4(bh, ad);
                ldsm4(bl, ad + (OFF_W1L - OFF_W1H));
                mma6(acc + 8 * ntp, x1h[s], x1l[s], bh, bl);
            }
        }

        // ---- bias + relu -> x2 fragments ----
        u32 x2h[8][4], x2l[8][4];
        #pragma unroll
        for (int s = 0; s < 8; ++s) {
            int n0 = 16 * s + kc;
            float bb00 = b1s[n0], bb01 = b1s[n0 + 1], bb10 = b1s[n0 + 8], bb11 = b1s[n0 + 9];
            const float* A = acc + 8 * s;
            x2h[s][0] = packhl(relu(A[0] + bb00), relu(A[1] + bb01), x2l[s][0]);
            x2h[s][1] = packhl(relu(A[2] + bb00), relu(A[3] + bb01), x2l[s][1]);
            x2h[s][2] = packhl(relu(A[4] + bb10), relu(A[5] + bb11), x2l[s][2]);
            x2h[s][3] = packhl(relu(A[6] + bb10), relu(A[7] + bb11), x2l[s][3]);
        }

        // ---- GEMM_D over only the needed m-groups (warp-uniform) ----
        int   mlist[3] = { mA, 7, mB };
        float c0l[3]   = { cA0, c70, cB0 };
        float c1l[3]   = { cA1, c71, cB1 };
        const int ng = hasB ? 3 : 2;

        float vout0[8], vout1[8];
        #pragma unroll
        for (int i = 0; i < 8; ++i) { vout0[i] = 0.f; vout1[i] = 0.f; }

        for (int grp = 0; grp < ng; ++grp) {
            const int m = mlist[grp];
            const float c0 = c0l[grp], c1 = c1l[grp];
            u32 rbd[2], sxd[2];
            #pragma unroll
            for (int ntp = 0; ntp < 2; ++ntp) {
                int n = m * 32 + (2 * ntp + (g >> 1)) * 8 + lr;
                rbd[ntp] = sb + OFF_TH + n * 256;
                sxd[ntp] = (u32)(n & 7) << 4;
            }
            float accd[16];
            #pragma unroll
            for (int i = 0; i < 16; ++i) accd[i] = 0.f;
            #pragma unroll
            for (int s = 0; s < 8; ++s) {
                u32 kx = ((u32)s << 5) ^ kxor;
                #pragma unroll
                for (int ntp = 0; ntp < 2; ++ntp) {
                    u32 ad = rbd[ntp] + (kx ^ sxd[ntp]);
                    u32 bh[4], bl[4];
                    ldsm4(bh, ad);
                    ldsm4(bl, ad + (OFF_TL - OFF_TH));
                    mma6(accd + 8 * ntp, x2h[s], x2l[s], bh, bl);
                }
            }
            #pragma unroll
            for (int ntp = 0; ntp < 2; ++ntp)
                #pragma unroll
                for (int tile = 0; tile < 2; ++tile) {
                    int o = 16 * ntp + 8 * tile + kc;
                    float tb0 = Tbs[m * 32 + o], tb1 = Tbs[m * 32 + o + 1];
                    const float* A = accd + 8 * ntp + 4 * tile;
                    int vi = 4 * ntp + 2 * tile;
                    vout0[vi]     = fmaf(c0, A[0] + tb0, vout0[vi]);
                    vout0[vi + 1] = fmaf(c0, A[1] + tb1, vout0[vi + 1]);
                    vout1[vi]     = fmaf(c1, A[2] + tb0, vout1[vi]);
                    vout1[vi + 1] = fmaf(c1, A[3] + tb1, vout1[vi + 1]);
                }
        }

        // ---- store ----
        #pragma unroll
        for (int ntp = 0; ntp < 2; ++ntp)
            #pragma unroll
            for (int tile = 0; tile < 2; ++tile) {
                int o = 16 * ntp + 8 * tile + kc;
                int vi = 4 * ntp + 2 * tile;
                *(float2*)(out + ge0 * 32 + o) = make_float2(vout0[vi], vout0[vi + 1]);
                *(float2*)(out + ge1 * 32 + o) = make_float2(vout1[vi], vout1[vi + 1]);
            }
    }
}

extern "C" void kernel_launch(void* const* d_in, const int* in_sizes, int n_in,
                              void* d_out, int out_size)
{
    const float* h_w  = (const float*)d_in[1];
    const float* e_vw = (const float*)d_in[2];
    const float* W0   = (const float*)d_in[3];
    const float* b0   = (const float*)d_in[4];
    const float* W1   = (const float*)d_in[5];
    const float* b1   = (const float*)d_in[6];
    const float* W2   = (const float*)d_in[7];
    const float* b2   = (const float*)d_in[8];
    float* out = (float*)d_out;

    prep<<<200, 256>>>(W0, W1, b0, b1, W2, b2);

    cudaFuncSetAttribute(msg_kernel, cudaFuncAttributeMaxDynamicSharedMemorySize, SMEM_BYTES);
    msg_kernel<<<GRID, 256, SMEM_BYTES>>>(h_w, e_vw, out);
}

// round 8
// speedup vs baseline: 1.0047x; 1.0047x over previous
#include <cuda_runtime.h>
#include <cuda_bf16.h>
#include <cstdint>

typedef unsigned int u32;

#define E_TOT   200000
#define GRID    148
#define NTHR    384
#define NWARP   12
#define UNITS   12500           // 20 r-values x 625 b-blocks of 16
#define USTRIDE (GRID * NWARP)

#define OFF_W0H 0
#define OFF_W0L 4096
#define OFF_W1H 8192
#define OFF_W1L 40960
#define OFF_TH  73728
#define OFF_TL  139264
#define OFF_TB  204800
#define OFF_B0  205824
#define OFF_B1  206336
#define SMEM_BYTES 206848

__device__ uint4 gWimg[SMEM_BYTES / 16];

// XOR-swizzled byte offset within a 256B-row bf16 image: row n, col k (0..127)
__host__ __device__ __forceinline__ u32 sw_off(int n, int k) {
    int chunk = k >> 3;
    return (u32)(n * 256 + (((chunk ^ (n & 7)) << 4) | ((k & 7) << 1)));
}

__device__ __forceinline__ void put_hl(u32 offh, u32 offl, u32 boff, float v) {
    char* img = (char*)gWimg;
    __nv_bfloat16 h = __float2bfloat16(v);
    __nv_bfloat16 l = __float2bfloat16(v - __bfloat162float(h));
    *(__nv_bfloat16*)(img + offh + boff) = h;
    *(__nv_bfloat16*)(img + offl + boff) = l;
}

// blocks 0..71: W0/W1 images + biases. blocks 72..103: T' rows (m*32+o) + Tb.
__global__ void prep(const float* __restrict__ W0, const float* __restrict__ W1,
                     const float* __restrict__ b0, const float* __restrict__ b1,
                     const float* __restrict__ W2, const float* __restrict__ b2)
{
    int blk = blockIdx.x, tid = threadIdx.x;
    if (blk < 72) {
        int id = blk * 256 + tid;
        if (id < 2048) {                   // W0 [128n][16k], 32B rows, no swizzle
            int n = id >> 4, k = id & 15;
            put_hl(OFF_W0H, OFF_W0L, (u32)(n * 32 + k * 2), W0[id]);
        } else if (id < 2048 + 16384) {    // W1 [128n][128k], swizzled
            int j = id - 2048;
            put_hl(OFF_W1H, OFF_W1L, sw_off(j >> 7, j & 127), W1[j]);
        }
        if (id < 128) {
            *(float*)((char*)gWimg + OFF_B0 + id * 4) = b0[id];
            *(float*)((char*)gWimg + OFF_B1 + id * 4) = b1[id];
        }
    } else {
        int o = blk - 72, j = tid & 127;
        if (tid < 128) {
            float s = 0.f;
            #pragma unroll
            for (int i = 0; i < 32; ++i) {
                s += W2[(o * 32 + i) * 128 + j];
                if ((i & 3) == 3) put_hl(OFF_TH, OFF_TL, sw_off((i >> 2) * 32 + o, j), s);
            }
        } else if (tid == 128) {
            float sb = 0.f;
            #pragma unroll
            for (int i = 0; i < 32; ++i) {
                sb += b2[o * 32 + i];
                if ((i & 3) == 3)
                    *(float*)((char*)gWimg + OFF_TB + ((i >> 2) * 32 + o) * 4) = sb;
            }
        }
    }
}

// ---------------------------------------------------------------------------
__device__ __forceinline__ u32 smem_u32(const void* p) {
    u32 a;
    asm("{ .reg .u64 t; cvta.to.shared.u64 t, %1; cvt.u32.u64 %0, t; }" : "=r"(a) : "l"(p));
    return a;
}
__device__ __forceinline__ void ldsm4(u32* r, u32 a) {
    asm volatile("ldmatrix.sync.aligned.m8n8.x4.shared.b16 {%0,%1,%2,%3}, [%4];"
        : "=r"(r[0]), "=r"(r[1]), "=r"(r[2]), "=r"(r[3]) : "r"(a));
}
__device__ __forceinline__ void mma(float* d, const u32* a, const u32* b) {
    asm volatile("mma.sync.aligned.m16n8k16.row.col.f32.bf16.bf16.f32 "
        "{%0,%1,%2,%3}, {%4,%5,%6,%7}, {%8,%9}, {%0,%1,%2,%3};"
        : "+f"(d[0]), "+f"(d[1]), "+f"(d[2]), "+f"(d[3])
        : "r"(a[0]), "r"(a[1]), "r"(a[2]), "r"(a[3]), "r"(b[0]), "r"(b[1]));
}
__device__ __forceinline__ void mma6(float* acc, const u32* ah, const u32* al,
                                     const u32* bh, const u32* bl)
{
    mma(acc,     ah, bh);
    mma(acc + 4, ah, bh + 2);
    mma(acc,     ah, bl);
    mma(acc + 4, ah, bl + 2);
    mma(acc,     al, bh);
    mma(acc + 4, al, bh + 2);
}
__device__ __forceinline__ u32 packhl(float f0, float f1, u32& lo) {
    u32 h;
    asm("cvt.rn.bf16x2.f32 %0, %1, %2;" : "=r"(h) : "f"(f1), "f"(f0));
    float h0 = __uint_as_float(h << 16);
    float h1 = __uint_as_float(h & 0xffff0000u);
    asm("cvt.rn.bf16x2.f32 %0, %1, %2;" : "=r"(lo) : "f"(f1 - h1), "f"(f0 - h0));
    return h;
}
__device__ __forceinline__ float relu(float x) { return fmaxf(x, 0.f); }

__global__ void __launch_bounds__(NTHR, 1)
msg_kernel(const float* __restrict__ h_w, const float* __restrict__ e_vw,
           float* __restrict__ out)
{
    extern __shared__ unsigned char sraw[];
    const int t = threadIdx.x, w = t >> 5, lane = t & 31;
    const int lr = lane & 7, g = lane >> 3, q = lane & 3;
    const int kc = 2 * q;
    const int el = lane >> 2;

    // stage weight image (202KB)
    {
        uint4* dst = (uint4*)sraw;
        for (int i = t; i < SMEM_BYTES / 16; i += NTHR) dst[i] = gWimg[i];
    }
    __syncthreads();

    const u32 sb = smem_u32(sraw);
    const float* b0s = (const float*)(sraw + OFF_B0);
    const float* b1s = (const float*)(sraw + OFF_B1);
    const float* Tbs = (const float*)(sraw + OFF_TB);

    // GEMM1 per-ntp address bases (unit-invariant)
    u32 rb1[8], sx1[8];
    #pragma unroll
    for (int ntp = 0; ntp < 8; ++ntp) {
        int n = (2 * ntp + (g >> 1)) * 8 + lr;
        rb1[ntp] = sb + OFF_W1H + n * 256;
        sx1[ntp] = (u32)(n & 7) << 4;
    }
    const u32 kxor = (u32)(g & 1) << 4;

    const int u0i = blockIdx.x * NWARP + w;

    // ---- initial prefetch (e rows + h_w values) ----
    float2 Pe[4];
    float Ph[6];
    {
        int uu = (u0i < UNITS) ? u0i : 0;
        int r = uu % 20, bblk = uu / 20;
        int nb0 = bblk * 16 + el, nb1 = nb0 + 8;
        size_t ge0 = (size_t)nb0 * 20 + r, ge1 = (size_t)nb1 * 20 + r;
        int rm = (r * 32) % 20;
        int i1 = rm ? 20 - rm : 20;
        int v0 = (r * 32) / 20;
        bool hasB = (i1 + 20) < 32;
        Pe[0] = *(const float2*)(e_vw + ge0 * 16 + kc);
        Pe[1] = *(const float2*)(e_vw + ge0 * 16 + kc + 8);
        Pe[2] = *(const float2*)(e_vw + ge1 * 16 + kc);
        Pe[3] = *(const float2*)(e_vw + ge1 * 16 + kc + 8);
        Ph[0] = h_w[nb0 * 32 + v0]; Ph[1] = h_w[nb0 * 32 + v0 + 1];
        Ph[2] = hasB ? h_w[nb0 * 32 + v0 + 2] : 0.f;
        Ph[3] = h_w[nb1 * 32 + v0]; Ph[4] = h_w[nb1 * 32 + v0 + 1];
        Ph[5] = hasB ? h_w[nb1 * 32 + v0 + 2] : 0.f;
    }

    for (int u = u0i; u < UNITS; u += USTRIDE) {
        const int r = u % 20, bblk = u / 20;
        const int nb0 = bblk * 16 + el;
        const size_t ge0 = (size_t)nb0 * 20 + r;
        const size_t ge1 = ge0 + 160;

        // ---- warp-uniform telescoping structure ----
        const int rm = (r * 32) % 20;
        const int i1 = rm ? 20 - rm : 20;
        const int mA = (i1 >> 2) - 1;
        const bool hasB = (i1 + 20) < 32;
        const int mB = hasB ? ((i1 + 20) >> 2) - 1 : 7;

        // ---- consume prefetched values ----
        float cA0 = Ph[0] - Ph[1], cA1 = Ph[3] - Ph[4];
        float cB0 = 0.f, cB1 = 0.f, c70 = Ph[1], c71 = Ph[4];
        if (hasB) { cB0 = Ph[1] - Ph[2]; cB1 = Ph[4] - Ph[5]; c70 = Ph[2]; c71 = Ph[5]; }

        u32 ah[4], al[4];
        ah[0] = packhl(Pe[0].x, Pe[0].y, al[0]);
        ah[1] = packhl(Pe[2].x, Pe[2].y, al[1]);
        ah[2] = packhl(Pe[1].x, Pe[1].y, al[2]);
        ah[3] = packhl(Pe[3].x, Pe[3].y, al[3]);

        // ---- GEMM0 + GEMM1 in two N-halves each (acc[32]) ----
        u32 x1h[8][4], x1l[8][4];
        #pragma unroll
        for (int half = 0; half < 2; ++half) {
            float acc[32];
            #pragma unroll
            for (int n2 = 0; n2 < 4; ++n2) {      // init with bias
                int n0 = 16 * (half * 4 + n2) + kc;
                float bb00 = b0s[n0], bb01 = b0s[n0 + 1];
                float bb10 = b0s[n0 + 8], bb11 = b0s[n0 + 9];
                float* A = acc + 8 * n2;
                A[0] = bb00; A[1] = bb01; A[2] = bb00; A[3] = bb01;
                A[4] = bb10; A[5] = bb11; A[6] = bb10; A[7] = bb11;
            }
            #pragma unroll
            for (int n2 = 0; n2 < 4; ++n2) {
                int ntp = half * 4 + n2;
                int n = (2 * ntp + (g >> 1)) * 8 + lr;
                u32 ad = sb + OFF_W0H + n * 32 + (g & 1) * 16;
                u32 bh[4], bl[4];
                ldsm4(bh, ad);
                ldsm4(bl, ad + (OFF_W0L - OFF_W0H));
                mma6(acc + 8 * n2, ah, al, bh, bl);
            }
            #pragma unroll
            for (int n2 = 0; n2 < 4; ++n2) {      // relu + split
                int s = half * 4 + n2;
                const float* A = acc + 8 * n2;
                x1h[s][0] = packhl(relu(A[0]), relu(A[1]), x1l[s][0]);
                x1h[s][1] = packhl(relu(A[2]), relu(A[3]), x1l[s][1]);
                x1h[s][2] = packhl(relu(A[4]), relu(A[5]), x1l[s][2]);
                x1h[s][3] = packhl(relu(A[6]), relu(A[7]), x1l[s][3]);
            }
        }

        u32 x2h[8][4], x2l[8][4];
        #pragma unroll
        for (int half = 0; half < 2; ++half) {
            float acc[32];
            #pragma unroll
            for (int n2 = 0; n2 < 4; ++n2) {
                int n0 = 16 * (half * 4 + n2) + kc;
                float bb00 = b1s[n0], bb01 = b1s[n0 + 1];
                float bb10 = b1s[n0 + 8], bb11 = b1s[n0 + 9];
                float* A = acc + 8 * n2;
                A[0] = bb00; A[1] = bb01; A[2] = bb00; A[3] = bb01;
                A[4] = bb10; A[5] = bb11; A[6] = bb10; A[7] = bb11;
            }
            #pragma unroll
            for (int s = 0; s < 8; ++s) {
                u32 kx = ((u32)s << 5) ^ kxor;
                #pragma unroll
                for (int n2 = 0; n2 < 4; ++n2) {
                    int ntp = half * 4 + n2;
                    u32 ad = rb1[ntp] + (kx ^ sx1[ntp]);
                    u32 bh[4], bl[4];
                    ldsm4(bh, ad);
                    ldsm4(bl, ad + (OFF_W1L - OFF_W1H));
                    mma6(acc + 8 * n2, x1h[s], x1l[s], bh, bl);
                }
            }
            #pragma unroll
            for (int n2 = 0; n2 < 4; ++n2) {
                int s = half * 4 + n2;
                const float* A = acc + 8 * n2;
                x2h[s][0] = packhl(relu(A[0]), relu(A[1]), x2l[s][0]);
                x2h[s][1] = packhl(relu(A[2]), relu(A[3]), x2l[s][1]);
                x2h[s][2] = packhl(relu(A[4]), relu(A[5]), x2l[s][2]);
                x2h[s][3] = packhl(relu(A[6]), relu(A[7]), x2l[s][3]);
            }
        }

        // ---- prefetch next unit (hidden behind GEMM_D) ----
        {
            int un = u + USTRIDE;
            if (un < UNITS) {
                int rn = un % 20, bbn = un / 20;
                int n0 = bbn * 16 + el, n1 = n0 + 8;
                size_t g0 = (size_t)n0 * 20 + rn, g1 = (size_t)n1 * 20 + rn;
                int rmn = (rn * 32) % 20;
                int i1n = rmn ? 20 - rmn : 20;
                int v0n = (rn * 32) / 20;
                bool hBn = (i1n + 20) < 32;
                Pe[0] = *(const float2*)(e_vw + g0 * 16 + kc);
                Pe[1] = *(const float2*)(e_vw + g0 * 16 + kc + 8);
                Pe[2] = *(const float2*)(e_vw + g1 * 16 + kc);
                Pe[3] = *(const float2*)(e_vw + g1 * 16 + kc + 8);
                Ph[0] = h_w[n0 * 32 + v0n]; Ph[1] = h_w[n0 * 32 + v0n + 1];
                Ph[2] = hBn ? h_w[n0 * 32 + v0n + 2] : 0.f;
                Ph[3] = h_w[n1 * 32 + v0n]; Ph[4] = h_w[n1 * 32 + v0n + 1];
                Ph[5] = hBn ? h_w[n1 * 32 + v0n + 2] : 0.f;
            }
        }

        // ---- GEMM_D over only the needed m-groups (warp-uniform) ----
        int   mlist[3] = { mA, 7, mB };
        float c0l[3]   = { cA0, c70, cB0 };
        float c1l[3]   = { cA1, c71, cB1 };
        const int ng = hasB ? 3 : 2;

        float vout0[8], vout1[8];
        #pragma unroll
        for (int i = 0; i < 8; ++i) { vout0[i] = 0.f; vout1[i] = 0.f; }

        for (int grp = 0; grp < ng; ++grp) {
            const int m = mlist[grp];
            const float c0 = c0l[grp], c1 = c1l[grp];
            float accd[16];
            #pragma unroll
            for (int ntp = 0; ntp < 2; ++ntp)    // init with Tb
                #pragma unroll
                for (int tile = 0; tile < 2; ++tile) {
                    int o = 16 * ntp + 8 * tile + kc;
                    float tb0 = Tbs[m * 32 + o], tb1 = Tbs[m * 32 + o + 1];
                    float* A = accd + 8 * ntp + 4 * tile;
                    A[0] = tb0; A[1] = tb1; A[2] = tb0; A[3] = tb1;
                }
            u32 rbd[2], sxd[2];
            #pragma unroll
            for (int ntp = 0; ntp < 2; ++ntp) {
                int n = m * 32 + (2 * ntp + (g >> 1)) * 8 + lr;
                rbd[ntp] = sb + OFF_TH + n * 256;
                sxd[ntp] = (u32)(n & 7) << 4;
            }
            #pragma unroll
            for (int s = 0; s < 8; ++s) {
                u32 kx = ((u32)s << 5) ^ kxor;
                #pragma unroll
                for (int ntp = 0; ntp < 2; ++ntp) {
                    u32 ad = rbd[ntp] + (kx ^ sxd[ntp]);
                    u32 bh[4], bl[4];
                    ldsm4(bh, ad);
                    ldsm4(bl, ad + (OFF_TL - OFF_TH));
                    mma6(accd + 8 * ntp, x2h[s], x2l[s], bh, bl);
                }
            }
            #pragma unroll
            for (int ntp = 0; ntp < 2; ++ntp)
                #pragma unroll
                for (int tile = 0; tile < 2; ++tile) {
                    const float* A = accd + 8 * ntp + 4 * tile;
                    int vi = 4 * ntp + 2 * tile;
                    vout0[vi]     = fmaf(c0, A[0], vout0[vi]);
                    vout0[vi + 1] = fmaf(c0, A[1], vout0[vi + 1]);
                    vout1[vi]     = fmaf(c1, A[2], vout1[vi]);
                    vout1[vi + 1] = fmaf(c1, A[3], vout1[vi + 1]);
                }
        }

        // ---- store ----
        #pragma unroll
        for (int ntp = 0; ntp < 2; ++ntp)
            #pragma unroll
            for (int tile = 0; tile < 2; ++tile) {
                int o = 16 * ntp + 8 * tile + kc;
                int vi = 4 * ntp + 2 * tile;
                *(float2*)(out + ge0 * 32 + o) = make_float2(vout0[vi], vout0[vi + 1]);
                *(float2*)(out + ge1 * 32 + o) = make_float2(vout1[vi], vout1[vi + 1]);
            }
    }
}

extern "C" void kernel_launch(void* const* d_in, const int* in_sizes, int n_in,
                              void* d_out, int out_size)
{
    const float* h_w  = (const float*)d_in[1];
    const float* e_vw = (const float*)d_in[2];
    const float* W0   = (const float*)d_in[3];
    const float* b0   = (const float*)d_in[4];
    const float* W1   = (const float*)d_in[5];
    const float* b1   = (const float*)d_in[6];
    const float* W2   = (const float*)d_in[7];
    const float* b2   = (const float*)d_in[8];
    float* out = (float*)d_out;

    prep<<<104, 256>>>(W0, W1, b0, b1, W2, b2);

    cudaFuncSetAttribute(msg_kernel, cudaFuncAttributeMaxDynamicSharedMemorySize, SMEM_BYTES);
    msg_kernel<<<GRID, NTHR, SMEM_BYTES>>>(h_w, e_vw, out);
}